// round 7
// baseline (speedup 1.0000x reference)
#include <cuda_runtime.h>
#include <float.h>

// ConsensusAttention: b=8, n=1024 (32x32 grid), l=6, d=512, fp32.
// K1: symmetric pair dots + ||q||^2, kDC=32, double-buffered cp.async,
//     3 blocks/SM.
// K2: softmax stores (p,p) u64 pairs; key-stationary PV with f2 lanes:
//     inner pair = LDS.64 p2 + 1 fma.rn.f32x2 (3 instr incl v amortized).
//     kDC=32, cp.async staging, 77KB smem -> 3 blocks/SM.

namespace {
constexpr int kHW = 32;
constexpr int kN  = kHW * kHW;   // 1024
constexpr int kL  = 6;
constexpr int kB  = 8;
constexpr int kD  = 512;
constexpr int kQR = 4;
constexpr int kQN = kQR * kHW;   // 128
constexpr int kRow = kL * kD;    // 3072
constexpr int kBL = kB * kL;     // 48
constexpr float kScale = 0.04419417382415922f;  // 512^-0.5

constexpr int kDC = 32;          // d-chunk floats (both kernels)
constexpr int kNC = kD / kDC;    // 16
constexpr int kSlotF4 = 9;       // f4 per slot (32 floats + 4 pad)

// K1: double-buffered
constexpr int kKN1 = 7 * kHW;              // 224 slots
constexpr int kBuf1 = kKN1 * kSlotF4;      // 2016 f4 per buffer
constexpr int kSmem1 = 2 * kBuf1 * 16;     // 64512 B

// K2: single buffer + packed probs + rns
constexpr int kKN2 = 10 * kHW;             // 320 slots
constexpr int kVFloats2 = kKN2 * kSlotF4 * 4;          // 11520 floats
constexpr int kSmem2 = kVFloats2 * 4 + kQN * 29 * 8 + kKN2 * 4;  // 77056 B

__constant__ int c_dh[29] = { -3,
  -2,-2,-2,-2,-2,   -1,-1,-1,-1,-1,
   0, 0, 0, 0, 0, 0, 0,
   1, 1, 1, 1, 1,    2, 2, 2, 2, 2,   3 };
__constant__ int c_dw[29] = {  0,
  -2,-1, 0, 1, 2,   -2,-1, 0, 1, 2,
  -3,-2,-1, 0, 1, 2, 3,
  -2,-1, 0, 1, 2,   -2,-1, 0, 1, 2,   0 };

__host__ __device__ constexpr int nbBase(int r) {
    return r == 0 ? 0 : r == 1 ? 1 : r == 2 ? 6 : r == 3 ? 11
         : r == 4 ? 18 : r == 5 ? 23 : 28;
}
__host__ __device__ constexpr int dwMin(int r) {
    return (r == 0 || r == 6) ? 0 : (r == 3 ? -3 : -2);
}
__host__ __device__ constexpr int dwMax(int r) {
    return (r == 0 || r == 6) ? 0 : (r == 3 ? 3 : 2);
}
}  // namespace

__device__ float g_dots[kBL][32][kN];   // [b*l][nb][q]  raw dots
__device__ float g_rn[kBL][kN];         // 1/max(||v||,1e-12)

__device__ __forceinline__ void fma2(unsigned long long& acc,
                                     unsigned long long a,
                                     unsigned long long b) {
    asm("fma.rn.f32x2 %0, %1, %2, %0;" : "+l"(acc) : "l"(a), "l"(b));
}
__device__ __forceinline__ float2 up2(unsigned long long v) {
    float2 r;
    asm("mov.b64 {%0, %1}, %2;" : "=f"(r.x), "=f"(r.y) : "l"(v));
    return r;
}
__device__ __forceinline__ unsigned long long pk2(float p) {
    unsigned long long r;
    asm("mov.b64 %0, {%1, %1};" : "=l"(r) : "f"(p));
    return r;
}
__device__ __forceinline__ void cpa16(void* dst_smem, const void* src) {
    unsigned s = (unsigned)__cvta_generic_to_shared(dst_smem);
    asm volatile("cp.async.ca.shared.global [%0], [%1], 16;" :: "r"(s), "l"(src));
}
__device__ __forceinline__ void cpa_commit() {
    asm volatile("cp.async.commit_group;");
}
template <int N>
__device__ __forceinline__ void cpa_wait() {
    asm volatile("cp.async.wait_group %0;" :: "n"(N));
}

// ============================ Kernel 1: dots + norms ============================
__global__ void __launch_bounds__(256, 3)
k1_scores(const float* __restrict__ levels)
{
    extern __shared__ float smem[];
    float4* vb4 = reinterpret_cast<float4*>(smem);
    const ulonglong2* vbu = reinterpret_cast<const ulonglong2*>(smem);

    const int ht = blockIdx.x, l = blockIdx.y, b = blockIdx.z;
    const int h0 = ht * kQR;
    const int rows = min(kHW - 1, h0 + 6) - h0 + 1;
    const int kn = rows * kHW;
    const int t = threadIdx.x;

    const float* base = levels + ((size_t)((b * kN + h0 * kHW) * kL + l)) * kD;

    const int q = t & 127, half = t >> 7;
    const int qh = h0 + (q >> 5), qw = q & 31;
    const int nb0 = 15 + half * 7;   // half0: nbs 15..21, half1: 22..28

    int ka[7];
    bool kv[7];
#pragma unroll
    for (int k = 0; k < 7; k++) {
        const int dh = c_dh[nb0 + k], dw = c_dw[nb0 + k];
        const int hh = qh + dh, ww = qw + dw;
        kv[k] = (hh < kHW) & (ww >= 0) & (ww < kHW);
        const int hc = min(hh, kHW - 1);
        const int wc = min(max(ww, 0), kHW - 1);
        ka[k] = ((hc - h0) * kHW + wc) * kSlotF4;   // ulonglong2 units
    }
    const int qb = ((qh - h0) * kHW + qw) * kSlotF4;

    unsigned long long acc[7];
#pragma unroll
    for (int k = 0; k < 7; k++) acc[k] = 0ull;
    unsigned long long sq = 0ull;

    const int items = kn * 8;   // f4 per chunk

    // prefetch chunk 0
    for (int idx = t; idx < items; idx += 256) {
        const int s = idx >> 3, u = idx & 7;
        cpa16(vb4 + s * kSlotF4 + u, base + (size_t)s * kRow + (u << 2));
    }
    cpa_commit();

    for (int c = 0; c < kNC; c++) {
        if (c < kNC - 1) {
            const float* src = base + (c + 1) * kDC;
            float4* dst = vb4 + ((c + 1) & 1) * kBuf1;
            for (int idx = t; idx < items; idx += 256) {
                const int s = idx >> 3, u = idx & 7;
                cpa16(dst + s * kSlotF4 + u, src + (size_t)s * kRow + (u << 2));
            }
            cpa_commit();
            cpa_wait<1>();   // chunk c complete; c+1 may still be in flight
        } else {
            cpa_wait<0>();
        }
        __syncthreads();

        const ulonglong2* vb = vbu + (c & 1) * kBuf1;
#pragma unroll
        for (int f = 0; f < 8; f++) {
            const ulonglong2 qf = vb[qb + f];
            if (half == 0) { fma2(sq, qf.x, qf.x); fma2(sq, qf.y, qf.y); }
#pragma unroll
            for (int k = 0; k < 7; k++) {
                const ulonglong2 vf = vb[ka[k] + f];
                fma2(acc[k], qf.x, vf.x);
                fma2(acc[k], qf.y, vf.y);
            }
        }
        __syncthreads();   // all reads of buffer (c&1) done before c+2 staging
    }

    const int bl = b * kL + l;
    const int qglob = qh * kHW + qw;
#pragma unroll
    for (int k = 0; k < 7; k++) {
        if (kv[k]) {
            const float2 a = up2(acc[k]);
            const float d = a.x + a.y;
            const int nb = nb0 + k;
            const int jglob = (qh + c_dh[nb]) * kHW + (qw + c_dw[nb]);
            g_dots[bl][nb][qglob]      = d;
            g_dots[bl][28 - nb][jglob] = d;
        }
    }
    if (half == 0) {
        const float2 s2 = up2(sq);
        const float sqn = s2.x + s2.y;
        g_dots[bl][14][qglob] = sqn;      // self dot = ||q||^2
        g_rn[bl][qglob] = 1.f / fmaxf(sqrtf(sqn), 1e-12f);
    }
}

// ======================= Kernel 2: softmax + key-stationary P*V =======================
__global__ void __launch_bounds__(256, 3)
k2_out(const float* __restrict__ levels, float* __restrict__ out)
{
    extern __shared__ float smem[];
    float4* vb4 = reinterpret_cast<float4*>(smem);
    const unsigned long long* vbu =
        reinterpret_cast<const unsigned long long*>(smem);       // 18 u64/slot
    unsigned long long* pbuf =
        reinterpret_cast<unsigned long long*>(smem + kVFloats2); // [128][29] (p,p)
    float* rns = smem + kVFloats2 + kQN * 29 * 2;                // [320]

    const int ht = blockIdx.x, l = blockIdx.y, b = blockIdx.z;
    const int h0 = ht * kQR;
    const int kr0 = max(0, h0 - 3);
    const int kr1 = min(kHW - 1, h0 + 6);
    const int kn = (kr1 - kr0 + 1) * kHW;
    const int t = threadIdx.x;
    const int bl = b * kL + l;

    const float* base = levels + ((size_t)((b * kN + kr0 * kHW) * kL + l)) * kD;
    float*      obase = out    + ((size_t)((b * kN + h0  * kHW) * kL + l)) * kD;

    const int items = kn * 8;   // f4 per chunk

    // prefetch chunk 0 (separate region from rns/pbuf)
    for (int idx = t; idx < items; idx += 256) {
        const int s = idx >> 3, u = idx & 7;
        cpa16(vb4 + s * kSlotF4 + u, base + (size_t)s * kRow + (u << 2));
    }
    cpa_commit();

    for (int i = t; i < kn; i += 256) rns[i] = g_rn[bl][kr0 * kHW + i];
    __syncthreads();   // rns visible

    // ---------------- softmax: one thread per query; writes packed (p,p) ----------------
    if (t < kQN) {
        const int qh = h0 + (t >> 5), qw = t & 31;
        const int qglob = qh * kHW + qw;
        float sv[29];
        float smax = -FLT_MAX;
#pragma unroll
        for (int nb = 0; nb < 29; nb++) {
            const int hh = qh + c_dh[nb], ww = qw + c_dw[nb];
            const bool v = (hh >= 0) & (hh < kHW) & (ww >= 0) & (ww < kHW);
            const int slot = v ? (hh - kr0) * kHW + ww : 0;
            float s = -FLT_MAX;
            if (v) s = g_dots[bl][nb][qglob] * rns[slot] * kScale;
            sv[nb] = s;
            smax = fmaxf(smax, s);
        }
        float sum = 0.f;
#pragma unroll
        for (int nb = 0; nb < 29; nb++) {
            const float p = __expf(sv[nb] - smax);  // masked -> exactly 0
            sv[nb] = p;
            sum += p;
        }
        const float rs = 1.f / sum;
#pragma unroll
        for (int nb = 0; nb < 29; nb++)
            pbuf[t * 29 + nb] = pk2(sv[nb] * rs);
    }

    // ---------------- key-stationary P*V, f2 lanes ----------------
    // warp = (qrow, 16-query half); lane: sub = lane>>4 (8-query subgroup),
    // part = lane&15 (f2 slice of the 32-float chunk).
    const int wid = t >> 5, lane = t & 31;
    const int qrow = wid >> 1;
    const int qbase = (wid & 1) * 16;
    const int sub = lane >> 4;
    const int part = lane & 15;
    const int qoff = qbase + sub * 8;      // subgroup origin (0/8/16/24)
    const int qh = h0 + qrow;

    int rowb[7];
#pragma unroll
    for (int r = 0; r < 7; r++) {
        const int hh = min(max(qh + (r - 3), 0), kHW - 1);
        rowb[r] = (hh - kr0) * kHW * (kSlotF4 * 2);   // u64 units (18/slot)
    }
    int colb[14];
#pragma unroll
    for (int k = 0; k < 14; k++) {
        const int ww = min(max(qoff + k - 3, 0), kHW - 1);
        colb[k] = ww * (kSlotF4 * 2);
    }
    const unsigned long long* pq = pbuf + (qrow * kHW + qoff) * 29;

    cpa_wait<0>();
    __syncthreads();   // chunk 0 + pbuf visible

    for (int c = 0; c < kNC; c++) {
        unsigned long long acc[8];
#pragma unroll
        for (int qi = 0; qi < 8; qi++) acc[qi] = 0ull;

#pragma unroll
        for (int r = 0; r < 7; r++) {
#pragma unroll
            for (int k = 0; k < 14; k++) {
                const int lo = (dwMin(r) > k - 10) ? dwMin(r) : k - 10;
                const int hi = (dwMax(r) < k - 3)  ? dwMax(r) : k - 3;
                if (lo <= hi) {
                    const unsigned long long v = vbu[rowb[r] + colb[k] + part];
#pragma unroll
                    for (int dw = lo; dw <= hi; dw++) {
                        const int qi = k - 3 - dw;              // 0..7 compile-time
                        const int nb = nbBase(r) + dw - dwMin(r);
                        fma2(acc[qi], pq[qi * 29 + nb], v);     // LDS.64 bcast + FMA2
                    }
                }
            }
        }

#pragma unroll
        for (int qi = 0; qi < 8; qi++) {
            const int q = qrow * kHW + qoff + qi;
            *reinterpret_cast<unsigned long long*>(
                obase + (size_t)q * kRow + c * kDC + part * 2) = acc[qi];
        }

        if (c < kNC - 1) {
            __syncthreads();   // all reads of vbuf done
            const float* src = base + (c + 1) * kDC;
            for (int idx = t; idx < items; idx += 256) {
                const int s = idx >> 3, u = idx & 7;
                cpa16(vb4 + s * kSlotF4 + u, src + (size_t)s * kRow + (u << 2));
            }
            cpa_commit();
            cpa_wait<0>();
            __syncthreads();   // staged visible
        }
    }
}

extern "C" void kernel_launch(void* const* d_in, const int* in_sizes, int n_in,
                              void* d_out, int out_size)
{
    const float* levels = (const float*)d_in[0];
    // d_in[1] (non_local_mask) is a pure function of the fixed 32x32 geometry.
    float* out = (float*)d_out;

    cudaFuncSetAttribute(k1_scores,
                         cudaFuncAttributeMaxDynamicSharedMemorySize, kSmem1);
    cudaFuncSetAttribute(k2_out,
                         cudaFuncAttributeMaxDynamicSharedMemorySize, kSmem2);

    dim3 grid(kHW / kQR, kL, kB);   // (8, 6, 8)
    k1_scores<<<grid, 256, kSmem1>>>(levels);
    k2_out<<<grid, 256, kSmem2>>>(levels, out);
}

// round 8
// speedup vs baseline: 1.2929x; 1.2929x over previous
#include <cuda_runtime.h>
#include <float.h>

// ConsensusAttention: b=8, n=1024 (32x32 grid), l=6, d=512, fp32.
// K1: symmetric pair dots + ||q||^2, kDC=32, double-buffered cp.async (R7).
// K2: round-6 float4-lane key-stationary PV (kDC=64, 8-query subgroups share
//     each LDS.128 v-load; 1 p-load feeds 4 output floats) + cp.async staging.

namespace {
constexpr int kHW = 32;
constexpr int kN  = kHW * kHW;   // 1024
constexpr int kL  = 6;
constexpr int kB  = 8;
constexpr int kD  = 512;
constexpr int kQR = 4;
constexpr int kQN = kQR * kHW;   // 128
constexpr int kRow = kL * kD;    // 3072
constexpr int kBL = kB * kL;     // 48
constexpr float kScale = 0.04419417382415922f;  // 512^-0.5

// ---- K1: kDC=32, double-buffered ----
constexpr int kDC1 = 32;
constexpr int kNC1 = kD / kDC1;            // 16
constexpr int kSlotF4_1 = 9;               // f4 per slot
constexpr int kKN1 = 7 * kHW;              // 224 slots
constexpr int kBuf1 = kKN1 * kSlotF4_1;    // 2016 f4 per buffer
constexpr int kSmem1 = 2 * kBuf1 * 16;     // 64512 B

// ---- K2: kDC=64, float4 lanes ----
constexpr int kDC2 = 64;
constexpr int kNC2 = kD / kDC2;            // 8
constexpr int kKN2 = 10 * kHW;             // 320 slots
constexpr int kVS2 = 68;                   // floats/slot = 17 f4 (odd stride)
constexpr int kSmem2 = kKN2 * kVS2 * 4 + kQN * 29 * 4;  // 87040+14848=101888 B

__constant__ int c_dh[29] = { -3,
  -2,-2,-2,-2,-2,   -1,-1,-1,-1,-1,
   0, 0, 0, 0, 0, 0, 0,
   1, 1, 1, 1, 1,    2, 2, 2, 2, 2,   3 };
__constant__ int c_dw[29] = {  0,
  -2,-1, 0, 1, 2,   -2,-1, 0, 1, 2,
  -3,-2,-1, 0, 1, 2, 3,
  -2,-1, 0, 1, 2,   -2,-1, 0, 1, 2,   0 };

__host__ __device__ constexpr int nbBase(int r) {
    return r == 0 ? 0 : r == 1 ? 1 : r == 2 ? 6 : r == 3 ? 11
         : r == 4 ? 18 : r == 5 ? 23 : 28;
}
__host__ __device__ constexpr int dwMin(int r) {
    return (r == 0 || r == 6) ? 0 : (r == 3 ? -3 : -2);
}
__host__ __device__ constexpr int dwMax(int r) {
    return (r == 0 || r == 6) ? 0 : (r == 3 ? 3 : 2);
}
}  // namespace

__device__ float g_dots[kBL][32][kN];   // [b*l][nb][q]  raw dots
__device__ float g_rn[kBL][kN];         // 1/max(||v||,1e-12)

__device__ __forceinline__ void fma2(unsigned long long& acc,
                                     unsigned long long a,
                                     unsigned long long b) {
    asm("fma.rn.f32x2 %0, %1, %2, %0;" : "+l"(acc) : "l"(a), "l"(b));
}
__device__ __forceinline__ float2 up2(unsigned long long v) {
    float2 r;
    asm("mov.b64 {%0, %1}, %2;" : "=f"(r.x), "=f"(r.y) : "l"(v));
    return r;
}
__device__ __forceinline__ unsigned long long pk2(float p) {
    unsigned long long r;
    asm("mov.b64 %0, {%1, %1};" : "=l"(r) : "f"(p));
    return r;
}
__device__ __forceinline__ void cpa16(void* dst_smem, const void* src) {
    unsigned s = (unsigned)__cvta_generic_to_shared(dst_smem);
    asm volatile("cp.async.ca.shared.global [%0], [%1], 16;" :: "r"(s), "l"(src));
}
__device__ __forceinline__ void cpa_commit() {
    asm volatile("cp.async.commit_group;");
}
template <int N>
__device__ __forceinline__ void cpa_wait() {
    asm volatile("cp.async.wait_group %0;" :: "n"(N));
}

// ============================ Kernel 1: dots + norms ============================
__global__ void __launch_bounds__(256, 3)
k1_scores(const float* __restrict__ levels)
{
    extern __shared__ float smem[];
    float4* vb4 = reinterpret_cast<float4*>(smem);
    const ulonglong2* vbu = reinterpret_cast<const ulonglong2*>(smem);

    const int ht = blockIdx.x, l = blockIdx.y, b = blockIdx.z;
    const int h0 = ht * kQR;
    const int rows = min(kHW - 1, h0 + 6) - h0 + 1;
    const int kn = rows * kHW;
    const int t = threadIdx.x;

    const float* base = levels + ((size_t)((b * kN + h0 * kHW) * kL + l)) * kD;

    const int q = t & 127, half = t >> 7;
    const int qh = h0 + (q >> 5), qw = q & 31;
    const int nb0 = 15 + half * 7;   // half0: nbs 15..21, half1: 22..28

    int ka[7];
    bool kv[7];
#pragma unroll
    for (int k = 0; k < 7; k++) {
        const int dh = c_dh[nb0 + k], dw = c_dw[nb0 + k];
        const int hh = qh + dh, ww = qw + dw;
        kv[k] = (hh < kHW) & (ww >= 0) & (ww < kHW);
        const int hc = min(hh, kHW - 1);
        const int wc = min(max(ww, 0), kHW - 1);
        ka[k] = ((hc - h0) * kHW + wc) * kSlotF4_1;
    }
    const int qb = ((qh - h0) * kHW + qw) * kSlotF4_1;

    unsigned long long acc[7];
#pragma unroll
    for (int k = 0; k < 7; k++) acc[k] = 0ull;
    unsigned long long sq = 0ull;

    const int items = kn * 8;   // f4 per chunk

    for (int idx = t; idx < items; idx += 256) {
        const int s = idx >> 3, u = idx & 7;
        cpa16(vb4 + s * kSlotF4_1 + u, base + (size_t)s * kRow + (u << 2));
    }
    cpa_commit();

    for (int c = 0; c < kNC1; c++) {
        if (c < kNC1 - 1) {
            const float* src = base + (c + 1) * kDC1;
            float4* dst = vb4 + ((c + 1) & 1) * kBuf1;
            for (int idx = t; idx < items; idx += 256) {
                const int s = idx >> 3, u = idx & 7;
                cpa16(dst + s * kSlotF4_1 + u, src + (size_t)s * kRow + (u << 2));
            }
            cpa_commit();
            cpa_wait<1>();
        } else {
            cpa_wait<0>();
        }
        __syncthreads();

        const ulonglong2* vb = vbu + (c & 1) * kBuf1;
#pragma unroll
        for (int f = 0; f < 8; f++) {
            const ulonglong2 qf = vb[qb + f];
            if (half == 0) { fma2(sq, qf.x, qf.x); fma2(sq, qf.y, qf.y); }
#pragma unroll
            for (int k = 0; k < 7; k++) {
                const ulonglong2 vf = vb[ka[k] + f];
                fma2(acc[k], qf.x, vf.x);
                fma2(acc[k], qf.y, vf.y);
            }
        }
        __syncthreads();
    }

    const int bl = b * kL + l;
    const int qglob = qh * kHW + qw;
#pragma unroll
    for (int k = 0; k < 7; k++) {
        if (kv[k]) {
            const float2 a = up2(acc[k]);
            const float d = a.x + a.y;
            const int nb = nb0 + k;
            const int jglob = (qh + c_dh[nb]) * kHW + (qw + c_dw[nb]);
            g_dots[bl][nb][qglob]      = d;
            g_dots[bl][28 - nb][jglob] = d;
        }
    }
    if (half == 0) {
        const float2 s2 = up2(sq);
        const float sqn = s2.x + s2.y;
        g_dots[bl][14][qglob] = sqn;      // self dot = ||q||^2
        g_rn[bl][qglob] = 1.f / fmaxf(sqrtf(sqn), 1e-12f);
    }
}

// ======================= Kernel 2: softmax + key-stationary P*V =======================
__global__ void __launch_bounds__(256, 2)
k2_out(const float* __restrict__ levels, float* __restrict__ out)
{
    extern __shared__ float smem[];
    float* vbuf = smem;                                  // [320][68]
    float* rns  = smem;                                  // ALIAS: dead after softmax
    float4* vb4 = reinterpret_cast<float4*>(vbuf);
    const ulonglong2* vbu2 = reinterpret_cast<const ulonglong2*>(vbuf);
    float* pbuf = smem + kKN2 * kVS2;                    // [128][29] f32

    const int ht = blockIdx.x, l = blockIdx.y, b = blockIdx.z;
    const int h0 = ht * kQR;
    const int kr0 = max(0, h0 - 3);
    const int kr1 = min(kHW - 1, h0 + 6);
    const int kn = (kr1 - kr0 + 1) * kHW;
    const int t = threadIdx.x;
    const int bl = b * kL + l;

    const float* base = levels + ((size_t)((b * kN + kr0 * kHW) * kL + l)) * kD;
    float*      obase = out    + ((size_t)((b * kN + h0  * kHW) * kL + l)) * kD;

    for (int i = t; i < kn; i += 256) rns[i] = g_rn[bl][kr0 * kHW + i];
    __syncthreads();

    // ---------------- softmax: one thread per query ----------------
    if (t < kQN) {
        const int qh = h0 + (t >> 5), qw = t & 31;
        const int qglob = qh * kHW + qw;
        float sv[29];
        float smax = -FLT_MAX;
#pragma unroll
        for (int nb = 0; nb < 29; nb++) {
            const int hh = qh + c_dh[nb], ww = qw + c_dw[nb];
            const bool v = (hh >= 0) & (hh < kHW) & (ww >= 0) & (ww < kHW);
            const int slot = v ? (hh - kr0) * kHW + ww : 0;
            float s = -FLT_MAX;
            if (v) s = g_dots[bl][nb][qglob] * rns[slot] * kScale;
            sv[nb] = s;
            smax = fmaxf(smax, s);
        }
        float sum = 0.f;
#pragma unroll
        for (int nb = 0; nb < 29; nb++) {
            const float p = __expf(sv[nb] - smax);  // masked -> exactly 0
            sv[nb] = p;
            sum += p;
        }
        const float rs = 1.f / sum;
#pragma unroll
        for (int nb = 0; nb < 29; nb++)
            pbuf[t * 29 + nb] = sv[nb] * rs;
    }

    // ---------------- key-stationary P*V, float4 lanes ----------------
    const int wid = t >> 5, lane = t & 31;
    const int qrow = wid >> 1;
    const int qbase = (wid & 1) * 16;
    const int sub = lane >> 4;
    const int part = lane & 15;
    const int qoff = qbase + sub * 8;      // subgroup origin (0/8/16/24)
    const int qh = h0 + qrow;

    int rowb[7];
#pragma unroll
    for (int r = 0; r < 7; r++) {
        const int hh = min(max(qh + (r - 3), 0), kHW - 1);
        rowb[r] = (hh - kr0) * kHW * 17;   // float4 units
    }
    int colb[14];
#pragma unroll
    for (int k = 0; k < 14; k++) {
        const int ww = min(max(qoff + k - 3, 0), kHW - 1);
        colb[k] = ww * 17;
    }
    const float* pq = pbuf + (qrow * kHW + qoff) * 29;

    for (int c = 0; c < kNC2; c++) {
        __syncthreads();   // vbuf reads done (c==0: rns dead, pbuf written)
        const float* src = base + c * kDC2;
        for (int idx = t; idx < kn * 16; idx += 256) {
            const int s = idx >> 4, u = idx & 15;
            cpa16(vb4 + s * 17 + u, src + (size_t)s * kRow + (u << 2));
        }
        cpa_commit();
        cpa_wait<0>();
        __syncthreads();

        unsigned long long ax[8], ay[8];
#pragma unroll
        for (int qi = 0; qi < 8; qi++) { ax[qi] = 0ull; ay[qi] = 0ull; }

#pragma unroll
        for (int r = 0; r < 7; r++) {
#pragma unroll
            for (int k = 0; k < 14; k++) {
                const int lo = (dwMin(r) > k - 10) ? dwMin(r) : k - 10;
                const int hi = (dwMax(r) < k - 3)  ? dwMax(r) : k - 3;
                if (lo <= hi) {
                    const ulonglong2 v = vbu2[rowb[r] + colb[k] + part];
#pragma unroll
                    for (int dw = lo; dw <= hi; dw++) {
                        const int qi = k - 3 - dw;              // 0..7 compile-time
                        const int nb = nbBase(r) + dw - dwMin(r);
                        const unsigned long long p2 = pk2(pq[qi * 29 + nb]);
                        fma2(ax[qi], p2, v.x);
                        fma2(ay[qi], p2, v.y);
                    }
                }
            }
        }

#pragma unroll
        for (int qi = 0; qi < 8; qi++) {
            const int q = qrow * kHW + qoff + qi;
            const float2 a0 = up2(ax[qi]), a1 = up2(ay[qi]);
            float4 o; o.x = a0.x; o.y = a0.y; o.z = a1.x; o.w = a1.y;
            *reinterpret_cast<float4*>(
                obase + (size_t)q * kRow + c * kDC2 + part * 4) = o;
        }
    }
}

extern "C" void kernel_launch(void* const* d_in, const int* in_sizes, int n_in,
                              void* d_out, int out_size)
{
    const float* levels = (const float*)d_in[0];
    // d_in[1] (non_local_mask) is a pure function of the fixed 32x32 geometry.
    float* out = (float*)d_out;

    cudaFuncSetAttribute(k1_scores,
                         cudaFuncAttributeMaxDynamicSharedMemorySize, kSmem1);
    cudaFuncSetAttribute(k2_out,
                         cudaFuncAttributeMaxDynamicSharedMemorySize, kSmem2);

    dim3 grid(kHW / kQR, kL, kB);   // (8, 6, 8)
    k1_scores<<<grid, 256, kSmem1>>>(levels);
    k2_out<<<grid, 256, kSmem2>>>(levels, out);
}